// round 11
// baseline (speedup 1.0000x reference)
#include <cuda_runtime.h>
#include <cstdint>

#define DD    2048
#define NBLK  16
#define BATCH 32

// Scratch (no allocations allowed -> __device__ globals; rewritten every launch)
__device__ int   g_cnt[NBLK];
__device__ int   g_idx[NBLK * 32];
__device__ float g_gval[NBLK * 32];
__device__ int   g_items[64];      // nb | (chunk << 8), dense
__device__ int   g_nitems;

// ---------------------------------------------------------------------------
// Kernel 1: CTA 0 computes ALL gates (warp = batch) + builds the worklist.
// CTAs 1..32 fill out[b] with bias (inactive (b,i) outputs are exactly bias).
// ---------------------------------------------------------------------------
__global__ __launch_bounds__(1024) void gate_kernel(
    const float* __restrict__ x, const float* __restrict__ gw,
    const float* __restrict__ gb, const float* __restrict__ bias,
    float* __restrict__ out)
{
    if (blockIdx.x > 0) {           // bias fill for batch blockIdx.x-1
        const int b = blockIdx.x - 1;
        if (threadIdx.x < 512)
            ((float4*)(out + (size_t)b * DD))[threadIdx.x] =
                ((const float4*)bias)[threadIdx.x];
        return;
    }

    __shared__ float sgate[BATCH][NBLK + 1];
    const int tid  = threadIdx.x;
    const int wid  = tid >> 5;      // warp = batch
    const int lane = tid & 31;

    {
        const int b = wid;
        const float* xr = x + (size_t)b * DD;
        float p[NBLK];
#pragma unroll
        for (int j = 0; j < NBLK; j++) p[j] = 0.f;

#pragma unroll 4
        for (int r = 0; r < 64; r++) {
            const int k = r * 32 + lane;
            const float xv = xr[k];
            const float4* gr = (const float4*)(gw + (size_t)k * NBLK);
            const float4 w0 = gr[0], w1 = gr[1], w2 = gr[2], w3 = gr[3];
            p[0]  += xv * w0.x;  p[1]  += xv * w0.y;  p[2]  += xv * w0.z;  p[3]  += xv * w0.w;
            p[4]  += xv * w1.x;  p[5]  += xv * w1.y;  p[6]  += xv * w1.z;  p[7]  += xv * w1.w;
            p[8]  += xv * w2.x;  p[9]  += xv * w2.y;  p[10] += xv * w2.z;  p[11] += xv * w2.w;
            p[12] += xv * w3.x;  p[13] += xv * w3.y;  p[14] += xv * w3.z;  p[15] += xv * w3.w;
        }

        // warp butterfly reduce (fixed order -> deterministic)
#pragma unroll
        for (int j = 0; j < NBLK; j++)
#pragma unroll
            for (int off = 16; off > 0; off >>= 1)
                p[j] += __shfl_xor_sync(0xffffffffu, p[j], off);

        if (lane == 0) {
            float v[NBLK];
#pragma unroll
            for (int j = 0; j < NBLK; j++)
                v[j] = 1.f / (1.f + expf(-(p[j] + gb[j])));
            unsigned mask = 0;   // drop 8 smallest; '<' => lowest index wins ties
            for (int it = 0; it < NBLK / 2; it++) {
                int best = 0; float bv = 3.4e38f;
                for (int j = 0; j < NBLK; j++)
                    if (!((mask >> j) & 1u) && v[j] < bv) { bv = v[j]; best = j; }
                mask |= 1u << best;
            }
#pragma unroll
            for (int j = 0; j < NBLK; j++)
                sgate[b][j] = ((mask >> j) & 1u) ? 0.f : v[j];
        }
    }
    __syncthreads();

    if (wid == 0) {                 // warp 0: compaction + worklist
        int cnt = 0;
        if (lane < NBLK) {
            for (int b = 0; b < BATCH; b++) {
                const float v = sgate[b][lane];
                if (v != 0.f) { g_idx[lane * 32 + cnt] = b; g_gval[lane * 32 + cnt] = v; cnt++; }
            }
            g_cnt[lane] = cnt;
            for (int s = cnt; s < 32; s++) { g_idx[lane * 32 + s] = 0; g_gval[lane * 32 + s] = 0.f; }
        }
        const int chunks = (lane < NBLK) ? ((cnt + 7) >> 3) : 0;
        int off = chunks;           // inclusive scan over lanes
#pragma unroll
        for (int d = 1; d < 32; d <<= 1) {
            const int t = __shfl_up_sync(0xffffffffu, off, d);
            if (lane >= d) off += t;
        }
        if (lane < NBLK)
            for (int c = 0; c < chunks; c++)
                g_items[off - chunks + c] = lane | (c << 8);
        if (lane == NBLK - 1) g_nitems = off;
    }
}

// ---------------------------------------------------------------------------
// Kernel 2: gated skinny GEMM, f32x2 FFMA, dense worklist indexing.
// CTA id -> item (id>>2) x col-tile (id&3). Active work = contiguous low ids
// -> modular placement spreads <=1 active CTA per SM.
// ---------------------------------------------------------------------------
__device__ __forceinline__ unsigned long long ffma2(
    unsigned long long a, unsigned long long b, unsigned long long c)
{
    unsigned long long d;
    asm("fma.rn.f32x2 %0, %1, %2, %3;" : "=l"(d) : "l"(a), "l"(b), "l"(c));
    return d;
}

__global__ __launch_bounds__(512, 1) void main_kernel(
    const float* __restrict__ x, const float* __restrict__ W,
    const float* __restrict__ bias, float* __restrict__ out)
{
    const int id     = blockIdx.x;
    const int item_i = id >> 2;
    if (item_i >= g_nitems) return;          // contiguous tail -> fast exit

    extern __shared__ float smem[];
    float* xs  = smem;              // 8 rows x 2048 floats (64 KB)
    float* red = smem;              // aliased after loop: 256 x 65 floats

    __shared__ int   s_bidx[8];
    __shared__ float s_gvl[8];

    const int item = g_items[item_i];
    const int nb   = item & 255;
    const int s0   = (item >> 8) * 8;        // first compacted slot
    const int c0   = nb * 128 + (id & 3) * 32;  // first output row of tile
    const int cnt  = g_cnt[nb];
    const int tid  = threadIdx.x;

    if (tid < 8) {
        s_bidx[tid] = g_idx[nb * 32 + s0 + tid];   // padded slots: b=0
        s_gvl[tid]  = g_gval[nb * 32 + s0 + tid];
    }
    __syncthreads();

    int bidx[8];
#pragma unroll
    for (int j = 0; j < 8; j++) bidx[j] = s_bidx[j];

    // stage x rows (coalesced float4 copies)
    for (int m = tid; m < 4096; m += 512) {
        const int s  = m >> 9;
        const int k4 = m & 511;
        ((float4*)(xs + s * DD))[k4] = ((const float4*)(x + (size_t)bidx[s] * DD))[k4];
    }
    __syncthreads();

    const int kg = tid & 63;        // 0..63 (lanes contiguous in k)
    const int cg = tid >> 6;        // 0..7

    // W rows for this thread's 4 output columns, viewed as k-pair (u64) stream
    const unsigned long long* w64 =
        (const unsigned long long*)(W + (size_t)(c0 + cg * 4) * DD);

    unsigned long long acc[8][4];
#pragma unroll
    for (int s = 0; s < 8; s++)
#pragma unroll
        for (int c = 0; c < 4; c++) acc[s][c] = 0ull;

    unsigned long long wA[4], wB[4];
#pragma unroll
    for (int c = 0; c < 4; c++) wA[c] = w64[c * 1024 + kg];

#pragma unroll 4
    for (int i = 0; i < 16; i++) {
        const int kidx = kg + i * 64;                 // k-pair index (k = 2*kidx)
        const int nidx = (kidx + 64) & 1023;          // next iter (wrap harmless)
#pragma unroll
        for (int c = 0; c < 4; c++) wB[c] = w64[c * 1024 + nidx];   // prefetch

        unsigned long long xv[8];
#pragma unroll
        for (int s = 0; s < 8; s++)
            xv[s] = *(const unsigned long long*)(xs + s * DD + (kidx << 1));

#pragma unroll
        for (int c = 0; c < 4; c++) {
            const unsigned long long wv = wA[c];
#pragma unroll
            for (int s = 0; s < 8; s++)
                acc[s][c] = ffma2(xv[s], wv, acc[s][c]);
        }
#pragma unroll
        for (int c = 0; c < 4; c++) wA[c] = wB[c];
    }
    __syncthreads();                // xs dead; alias as reduction buffer

    // horizontal add (even-k + odd-k), conflict-free partial store:
    // red[(s*32 + cg*4 + c)*65 + kg] -> bank (idx + kg) % 32, all distinct
#pragma unroll
    for (int s = 0; s < 8; s++) {
#pragma unroll
        for (int c = 0; c < 4; c++) {
            const unsigned long long v = acc[s][c];
            const float lo = __uint_as_float((unsigned)(v & 0xffffffffu));
            const float hi = __uint_as_float((unsigned)(v >> 32));
            red[(s * 32 + cg * 4 + c) * 65 + kg] = lo + hi;
        }
    }
    __syncthreads();

    if (tid < 256) {
        const int s  = tid >> 5;
        const int cp = tid & 31;
        const float* r = red + tid * 65;
        float a0 = 0.f, a1 = 0.f, a2 = 0.f, a3 = 0.f;
#pragma unroll
        for (int k = 0; k < 64; k += 4) {
            a0 += r[k]; a1 += r[k + 1]; a2 += r[k + 2]; a3 += r[k + 3];
        }
        const float sum = (a0 + a1) + (a2 + a3);
        if (s0 + s < cnt)
            out[(size_t)s_bidx[s] * DD + c0 + cp] = s_gvl[s] * sum + bias[c0 + cp];
    }
}

// ---------------------------------------------------------------------------
extern "C" void kernel_launch(void* const* d_in, const int* in_sizes, int n_in,
                              void* d_out, int out_size)
{
    (void)in_sizes; (void)n_in; (void)out_size;
    const float* x    = (const float*)d_in[0];
    const float* gw   = (const float*)d_in[1];
    const float* gb   = (const float*)d_in[2];
    const float* W    = (const float*)d_in[3];
    const float* bias = (const float*)d_in[4];
    float* out = (float*)d_out;

    static int smem_set = 0;
    if (!smem_set) {
        cudaFuncSetAttribute(main_kernel,
                             cudaFuncAttributeMaxDynamicSharedMemorySize,
                             256 * 65 * 4);   // 66560 B (xs 64 KB aliased inside)
        smem_set = 1;
    }

    gate_kernel<<<33, 1024>>>(x, gw, gb, bias, out);
    main_kernel<<<256, 512, 256 * 65 * 4>>>(x, W, bias, out);
}

// round 12
// speedup vs baseline: 4.0769x; 4.0769x over previous
#include <cuda_runtime.h>
#include <cstdint>

#define DD    2048
#define NBLK  16
#define BATCH 32

// Scratch (no allocations allowed -> __device__ globals; rewritten every launch)
__device__ float g_part[BATCH * 4 * NBLK];   // gate logit partials
__device__ int   g_arrive = 0;               // arrival counter (reset by finalize)
__device__ int   g_cnt[NBLK];
__device__ int   g_idx[NBLK * 32];
__device__ float g_gval[NBLK * 32];
__device__ int   g_items[64];                // nb | (chunk << 8), dense
__device__ int   g_nitems;

// ---------------------------------------------------------------------------
// Kernel 1: gate logit partials, K split 4 ways. grid=(32 batches, 4 slices).
// Bias-fills out. Last-arriving CTA finalizes gates + builds the worklist.
// ---------------------------------------------------------------------------
__global__ __launch_bounds__(256) void gate_kernel(
    const float* __restrict__ x, const float* __restrict__ gw,
    const float* __restrict__ gb, const float* __restrict__ bias,
    float* __restrict__ out)
{
    const int b    = blockIdx.x;
    const int sl   = blockIdx.y;
    const int tid  = threadIdx.x;
    const int base = sl * 512;

    __shared__ int lastflag;
    if (tid == 0) lastflag = 0;

    // bias fill for this (b, k-slice) range: 512 floats = 128 float4
    if (tid < 128)
        ((float4*)(out + (size_t)b * DD + base))[tid] = ((const float4*)(bias + base))[tid];

    float p[NBLK];
#pragma unroll
    for (int j = 0; j < NBLK; j++) p[j] = 0.f;

#pragma unroll
    for (int r = 0; r < 2; r++) {
        const int k = base + r * 256 + tid;
        const float xv = x[(size_t)b * DD + k];
        const float4* gr = (const float4*)(gw + (size_t)k * NBLK);
        const float4 w0 = gr[0], w1 = gr[1], w2 = gr[2], w3 = gr[3];
        p[0]  += xv * w0.x;  p[1]  += xv * w0.y;  p[2]  += xv * w0.z;  p[3]  += xv * w0.w;
        p[4]  += xv * w1.x;  p[5]  += xv * w1.y;  p[6]  += xv * w1.z;  p[7]  += xv * w1.w;
        p[8]  += xv * w2.x;  p[9]  += xv * w2.y;  p[10] += xv * w2.z;  p[11] += xv * w2.w;
        p[12] += xv * w3.x;  p[13] += xv * w3.y;  p[14] += xv * w3.z;  p[15] += xv * w3.w;
    }

    // warp butterfly reduce (fixed order -> deterministic)
#pragma unroll
    for (int j = 0; j < NBLK; j++)
#pragma unroll
        for (int off = 16; off > 0; off >>= 1)
            p[j] += __shfl_xor_sync(0xffffffffu, p[j], off);

    __shared__ float ws[8][NBLK + 1];
    if ((tid & 31) == 0) {
#pragma unroll
        for (int j = 0; j < NBLK; j++) ws[tid >> 5][j] = p[j];
    }
    __syncthreads();

    if (tid < NBLK) {
        float s = 0.f;
#pragma unroll
        for (int w = 0; w < 8; w++) s += ws[w][tid];
        g_part[((size_t)b * 4 + sl) * NBLK + tid] = s;
    }
    __syncthreads();

    // arrival protocol: last CTA of the 128 finalizes
    if (tid == 0) {
        __threadfence();
        if (atomicAdd(&g_arrive, 1) == 127) lastflag = 1;
    }
    __syncthreads();
    if (!lastflag) return;
    __threadfence();                         // acquire: see all partials

    // ---- finalize: thread = batch (32 threads), then warp-0 worklist ----
    __shared__ float sgate[BATCH][NBLK + 1];
    if (tid < BATCH) {
        float v[NBLK];
        const float4* gb4 = (const float4*)gb;
        {
            const float4 b0 = gb4[0], b1 = gb4[1], b2 = gb4[2], b3 = gb4[3];
            v[0]=b0.x; v[1]=b0.y; v[2]=b0.z;  v[3]=b0.w;
            v[4]=b1.x; v[5]=b1.y; v[6]=b1.z;  v[7]=b1.w;
            v[8]=b2.x; v[9]=b2.y; v[10]=b2.z; v[11]=b2.w;
            v[12]=b3.x; v[13]=b3.y; v[14]=b3.z; v[15]=b3.w;
        }
#pragma unroll
        for (int s = 0; s < 4; s++) {
            const float4* pp = (const float4*)(g_part + ((size_t)tid * 4 + s) * NBLK);
            const float4 p0 = pp[0], p1 = pp[1], p2 = pp[2], p3 = pp[3];
            v[0]+=p0.x;  v[1]+=p0.y;  v[2]+=p0.z;  v[3]+=p0.w;
            v[4]+=p1.x;  v[5]+=p1.y;  v[6]+=p1.z;  v[7]+=p1.w;
            v[8]+=p2.x;  v[9]+=p2.y;  v[10]+=p2.z; v[11]+=p2.w;
            v[12]+=p3.x; v[13]+=p3.y; v[14]+=p3.z; v[15]+=p3.w;
        }
#pragma unroll
        for (int j = 0; j < NBLK; j++) v[j] = 1.f / (1.f + expf(-v[j]));

        unsigned mask = 0;   // drop 8 smallest; '<' => lowest index wins ties
        for (int it = 0; it < NBLK / 2; it++) {
            int best = 0; float bv = 3.4e38f;
            for (int j = 0; j < NBLK; j++)
                if (!((mask >> j) & 1u) && v[j] < bv) { bv = v[j]; best = j; }
            mask |= 1u << best;
        }
#pragma unroll
        for (int j = 0; j < NBLK; j++)
            sgate[tid][j] = ((mask >> j) & 1u) ? 0.f : v[j];
    }
    __syncthreads();

    if (tid < 32) {                          // warp 0: compaction + worklist
        const int lane = tid;
        int cnt = 0;
        if (lane < NBLK) {
            for (int bb = 0; bb < BATCH; bb++) {
                const float v = sgate[bb][lane];
                if (v != 0.f) { g_idx[lane * 32 + cnt] = bb; g_gval[lane * 32 + cnt] = v; cnt++; }
            }
            g_cnt[lane] = cnt;
            for (int s = cnt; s < 32; s++) { g_idx[lane * 32 + s] = 0; g_gval[lane * 32 + s] = 0.f; }
        }
        const int chunks = (lane < NBLK) ? ((cnt + 7) >> 3) : 0;
        int off = chunks;                    // inclusive scan over lanes
#pragma unroll
        for (int d = 1; d < 32; d <<= 1) {
            const int t = __shfl_up_sync(0xffffffffu, off, d);
            if (lane >= d) off += t;
        }
        if (lane < NBLK)
            for (int c = 0; c < chunks; c++)
                g_items[off - chunks + c] = lane | (c << 8);
        if (lane == NBLK - 1) g_nitems = off;
        if (lane == 0) g_arrive = 0;         // reset for next graph replay
    }
}

// ---------------------------------------------------------------------------
// Kernel 2: gated skinny GEMM, f32x2 FFMA, depth-2 W prefetch, full unroll.
// CTA id -> item (id>>2) x col-tile (id&3); active work = contiguous low ids.
// ---------------------------------------------------------------------------
__device__ __forceinline__ unsigned long long ffma2(
    unsigned long long a, unsigned long long b, unsigned long long c)
{
    unsigned long long d;
    asm("fma.rn.f32x2 %0, %1, %2, %3;" : "=l"(d) : "l"(a), "l"(b), "l"(c));
    return d;
}

__global__ __launch_bounds__(512, 1) void main_kernel(
    const float* __restrict__ x, const float* __restrict__ W,
    const float* __restrict__ bias, float* __restrict__ out)
{
    const int id     = blockIdx.x;
    const int item_i = id >> 2;
    if (item_i >= g_nitems) return;          // contiguous tail -> fast exit

    extern __shared__ float smem[];
    float* xs  = smem;              // 8 rows x 2048 floats (64 KB)
    float* red = smem;              // aliased after loop: 256 x 65 floats

    __shared__ int   s_bidx[8];
    __shared__ float s_gvl[8];

    const int item = g_items[item_i];
    const int nb   = item & 255;
    const int s0   = (item >> 8) * 8;        // first compacted slot
    const int c0   = nb * 128 + (id & 3) * 32;  // first output row of tile
    const int cnt  = g_cnt[nb];
    const int tid  = threadIdx.x;

    if (tid < 8) {
        s_bidx[tid] = g_idx[nb * 32 + s0 + tid];   // padded slots: b=0
        s_gvl[tid]  = g_gval[nb * 32 + s0 + tid];
    }
    __syncthreads();

    int bidx[8];
#pragma unroll
    for (int j = 0; j < 8; j++) bidx[j] = s_bidx[j];

    // stage x rows (coalesced float4 copies)
    for (int m = tid; m < 4096; m += 512) {
        const int s  = m >> 9;
        const int k4 = m & 511;
        ((float4*)(xs + s * DD))[k4] = ((const float4*)(x + (size_t)bidx[s] * DD))[k4];
    }
    __syncthreads();

    const int kg = tid & 63;        // 0..63 (lanes contiguous in k)
    const int cg = tid >> 6;        // 0..7

    // W rows for this thread's 4 output columns, viewed as k-pair (u64) stream
    const unsigned long long* w64 =
        (const unsigned long long*)(W + (size_t)(c0 + cg * 4) * DD);

    unsigned long long acc[8][4];
#pragma unroll
    for (int s = 0; s < 8; s++)
#pragma unroll
        for (int c = 0; c < 4; c++) acc[s][c] = 0ull;

    unsigned long long wA[4], wB[4], wC[4];
#pragma unroll
    for (int c = 0; c < 4; c++) wA[c] = w64[c * 1024 + kg];
#pragma unroll
    for (int c = 0; c < 4; c++) wB[c] = w64[c * 1024 + kg + 64];

#pragma unroll
    for (int i = 0; i < 16; i++) {
        const int kidx = kg + i * 64;                 // k-pair index (k = 2*kidx)
        const int pidx = (kidx + 128) & 1023;         // depth-2 prefetch (wrap harmless)
#pragma unroll
        for (int c = 0; c < 4; c++) wC[c] = w64[c * 1024 + pidx];

        // first half: slots 0..3
        unsigned long long xv[4];
#pragma unroll
        for (int s = 0; s < 4; s++)
            xv[s] = *(const unsigned long long*)(xs + s * DD + (kidx << 1));
#pragma unroll
        for (int c = 0; c < 4; c++) {
            const unsigned long long wv = wA[c];
#pragma unroll
            for (int s = 0; s < 4; s++)
                acc[s][c] = ffma2(xv[s], wv, acc[s][c]);
        }
        // second half: slots 4..7
#pragma unroll
        for (int s = 0; s < 4; s++)
            xv[s] = *(const unsigned long long*)(xs + (s + 4) * DD + (kidx << 1));
#pragma unroll
        for (int c = 0; c < 4; c++) {
            const unsigned long long wv = wA[c];
#pragma unroll
            for (int s = 0; s < 4; s++)
                acc[s + 4][c] = ffma2(xv[s], wv, acc[s + 4][c]);
        }
        // rotate prefetch buffers (renamed away by full unroll)
#pragma unroll
        for (int c = 0; c < 4; c++) { wA[c] = wB[c]; wB[c] = wC[c]; }
    }
    __syncthreads();                // xs dead; alias as reduction buffer

    // horizontal add (even-k + odd-k), conflict-free partial store:
    // red[(s*32 + cg*4 + c)*65 + kg] -> bank (idx + kg) % 32, all distinct
#pragma unroll
    for (int s = 0; s < 8; s++) {
#pragma unroll
        for (int c = 0; c < 4; c++) {
            const unsigned long long v = acc[s][c];
            const float lo = __uint_as_float((unsigned)(v & 0xffffffffu));
            const float hi = __uint_as_float((unsigned)(v >> 32));
            red[(s * 32 + cg * 4 + c) * 65 + kg] = lo + hi;
        }
    }
    __syncthreads();

    if (tid < 256) {
        const int s  = tid >> 5;
        const int cp = tid & 31;
        const float* r = red + tid * 65;
        float a0 = 0.f, a1 = 0.f, a2 = 0.f, a3 = 0.f;
#pragma unroll
        for (int k = 0; k < 64; k += 4) {
            a0 += r[k]; a1 += r[k + 1]; a2 += r[k + 2]; a3 += r[k + 3];
        }
        const float sum = (a0 + a1) + (a2 + a3);
        if (s0 + s < cnt)
            out[(size_t)s_bidx[s] * DD + c0 + cp] = s_gvl[s] * sum + bias[c0 + cp];
    }
}

// ---------------------------------------------------------------------------
extern "C" void kernel_launch(void* const* d_in, const int* in_sizes, int n_in,
                              void* d_out, int out_size)
{
    (void)in_sizes; (void)n_in; (void)out_size;
    const float* x    = (const float*)d_in[0];
    const float* gw   = (const float*)d_in[1];
    const float* gb   = (const float*)d_in[2];
    const float* W    = (const float*)d_in[3];
    const float* bias = (const float*)d_in[4];
    float* out = (float*)d_out;

    static int smem_set = 0;
    if (!smem_set) {
        cudaFuncSetAttribute(main_kernel,
                             cudaFuncAttributeMaxDynamicSharedMemorySize,
                             256 * 65 * 4);   // 66560 B (xs 64 KB aliased inside)
        smem_set = 1;
    }

    gate_kernel<<<dim3(32, 4), 256>>>(x, gw, gb, bias, out);
    main_kernel<<<256, 512, 256 * 65 * 4>>>(x, W, bias, out);
}